// round 2
// baseline (speedup 1.0000x reference)
#include <cuda_runtime.h>
#include <cuda_bf16.h>
#include <math.h>

// Problem constants
#define B     256
#define V     100
#define C     40
#define E     128
#define H     100
#define G4    400      // 4*H
#define M_TOT 32768    // B*E

// ---------------- device scratch (no allocations allowed) ----------------
__device__ int   g_is64;
__device__ int   g_last[B];
__device__ float g_xseq[B * V * E];        // sum_embed, [b][v][e]  (== x_seq flat)
__device__ float g_xpart[M_TOT * G4];      // x @ W_ih^T + b_ih + b_hh, [m][g]
__device__ float g_trueh[B * E];

// ---------------- K-1: detect int32 vs int64 diag_x ----------------
// Probes odd 32-bit words at indices 1..511 (in-bounds either way).
// int64 values in [0,540) -> high words all zero; random int32 codes have
// P(all 256 odd words == 0) ~ (1/540)^256 ~ 0.
__global__ void k_detect(const int* __restrict__ p) {
    int v = p[2 * threadIdx.x + 1];
    int any = __syncthreads_or(v != 0);
    if (threadIdx.x == 0) g_is64 = any ? 0 : 1;
}

// ---------------- K0: last visit index per batch row ----------------
__global__ void k_last(const float* __restrict__ mask) {
    __shared__ int red[128];
    int b = blockIdx.x, tid = threadIdx.x;
    int best = -1;
    if (tid < V) {
        const float* mp = mask + (b * V + tid) * C;
        bool has = false;
        #pragma unroll 8
        for (int c = 0; c < C; c++) has |= (mp[c] != 0.f);
        if (has) best = tid;
    }
    red[tid] = best;
    __syncthreads();
    #pragma unroll
    for (int s = 64; s > 0; s >>= 1) {
        if (tid < s) red[tid] = max(red[tid], red[tid + s]);
        __syncthreads();
    }
    if (tid == 0) g_last[b] = (red[0] < 0) ? (V - 1) : red[0];  // idx -1 wraps
}

// ---------------- K1: masked embedding sum ----------------
// One warp per (b,v) pair; lane holds 4 of 128 embed dims as float4.
__global__ void k_embed(const int* __restrict__ diag,
                        const float* __restrict__ mask,
                        const float* __restrict__ table) {
    int is64 = g_is64;
    int p    = blockIdx.x * 8 + (threadIdx.x >> 5);   // (b*V + v)
    int lane = threadIdx.x & 31;
    const float4* tab4 = (const float4*)table;
    float4 acc = make_float4(0.f, 0.f, 0.f, 0.f);
    int base = p * C;
    #pragma unroll 4
    for (int c = 0; c < C; c++) {
        int idx = base + c;
        float m = mask[idx];
        int code = diag[idx << is64];     // low word of int64, or int32 directly
        if (m != 0.f) {
            float4 t = tab4[code * 32 + lane];
            acc.x += t.x * m; acc.y += t.y * m; acc.z += t.z * m; acc.w += t.w * m;
        }
    }
    ((float4*)g_xseq)[p * 32 + lane] = acc;
}

// ---------------- K2: x_part = x_seq @ W_ih^T + b_ih + b_hh ----------------
// Dense GEMM: A[32768,100] (g_xseq flat), Bmat[400,100]=W_ih, K=100.
// BM=128, BN=80, 256 threads, 8x5 micro-tile. K chunked in 2x50 so static
// shared memory stays at 42KB (no cudaFuncSetAttribute needed).
#define BM 128
#define BN 80
#define KC 50
#define ASTR 129
#define BSTR 81

__global__ void __launch_bounds__(256) k_gemm(const float* __restrict__ W,
                                              const float* __restrict__ bih,
                                              const float* __restrict__ bhh) {
    __shared__ float As[KC * ASTR];   // As[k*ASTR + m], 25.8KB
    __shared__ float Bs[KC * BSTR];   // Bs[k*BSTR + n], 16.2KB
    int tid = threadIdx.x;
    int m0 = blockIdx.x * BM;
    int n0 = blockIdx.y * BN;

    const float* Ag = g_xseq + m0 * 100;
    const float* Bg = W + n0 * 100;

    int tm = tid & 15;
    int tn = (tid >> 4) * 5;
    float acc[8][5];
    #pragma unroll
    for (int i = 0; i < 8; i++)
        #pragma unroll
        for (int j = 0; j < 5; j++) acc[i][j] = 0.f;

    #pragma unroll
    for (int kk = 0; kk < 2; kk++) {
        // load A chunk: BM*KC = 6400 elems; consecutive tids read 50-float
        // contiguous gmem runs (coalesced), store k-major for conflict-free FMA reads
        #pragma unroll
        for (int i = 0; i < 25; i++) {
            int li = tid + i * 256;
            int m = li / KC, k = li % KC;
            As[k * ASTR + m] = Ag[m * 100 + kk * KC + k];
        }
        // load B chunk: BN*KC = 4000 elems
        #pragma unroll
        for (int i = 0; i < 16; i++) {
            int li = tid + i * 256;
            if (li < BN * KC) {
                int n = li / KC, k = li % KC;
                Bs[k * BSTR + n] = Bg[n * 100 + kk * KC + k];
            }
        }
        __syncthreads();

        #pragma unroll 5
        for (int k = 0; k < KC; k++) {
            float a[8], bb[5];
            #pragma unroll
            for (int i = 0; i < 8; i++) a[i] = As[k * ASTR + tm + 16 * i];
            #pragma unroll
            for (int j = 0; j < 5; j++) bb[j] = Bs[k * BSTR + tn + j];
            #pragma unroll
            for (int i = 0; i < 8; i++)
                #pragma unroll
                for (int j = 0; j < 5; j++) acc[i][j] += a[i] * bb[j];
        }
        __syncthreads();
    }

    float bias[5];
    #pragma unroll
    for (int j = 0; j < 5; j++) bias[j] = bih[n0 + tn + j] + bhh[n0 + tn + j];
    #pragma unroll
    for (int i = 0; i < 8; i++) {
        int m = m0 + tm + 16 * i;
        #pragma unroll
        for (int j = 0; j < 5; j++)
            g_xpart[m * G4 + n0 + tn + j] = acc[i][j] + bias[j];
    }
}

// ---------------- K3: recurrent LSTM, one CTA per embed-row ----------------
// 800 threads = 2 threads per gate (k-split 50/50), W_hh rows in REGISTERS
// (SMEM streaming of 160KB/step would be crossbar-bound ~1250 cyc/step).
// h broadcast-read from SMEM as float4 (two aligned 50-float halves).
__device__ __forceinline__ float sigf(float x) {
    return 1.f / (1.f + __expf(-x));
}
__device__ __forceinline__ float tanhfast(float x) {
    x = fminf(fmaxf(x, -15.f), 15.f);   // avoid inf/inf NaN in __expf
    float e = __expf(2.f * x);
    return (e - 1.f) / (e + 1.f);
}

__global__ void __launch_bounds__(800, 1) k_rec(const float* __restrict__ Whh) {
    __shared__ __align__(16) float h_a[52];   // h[0..49] + zero pad
    __shared__ __align__(16) float h_b[52];   // h[50..99] + zero pad
    __shared__ float gates_s[G4];
    __shared__ int   last_s[B];

    int tid  = threadIdx.x;
    int e    = blockIdx.x;
    int g    = tid >> 1;
    int half = tid & 1;

    // weights in registers: 52 floats (pads zero so pad*h-pad contributes 0)
    float w[52];
    #pragma unroll
    for (int j = 0; j < 50; j++) w[j] = Whh[g * 100 + half * 50 + j];
    w[50] = 0.f; w[51] = 0.f;

    for (int i = tid; i < B; i += 800) last_s[i] = g_last[i];
    if (tid < 52) { h_a[tid] = 0.f; h_b[tid] = 0.f; }
    float c = 0.f;
    __syncthreads();

    const float* xp = g_xpart + e * G4 + g;   // per-step stride = E*G4
    float* th = g_trueh + e;

    #pragma unroll 1
    for (int t = 0; t < B; t++) {
        float xv = 0.f;
        if (!half) xv = __ldg(xp + t * (E * G4));

        const float4* hv4 = half ? (const float4*)h_b : (const float4*)h_a;
        float ax = 0.f, ay = 0.f, az = 0.f, aw = 0.f;
        #pragma unroll
        for (int j = 0; j < 13; j++) {
            float4 hv = hv4[j];
            ax += w[4 * j + 0] * hv.x;
            ay += w[4 * j + 1] * hv.y;
            az += w[4 * j + 2] * hv.z;
            aw += w[4 * j + 3] * hv.w;
        }
        float acc = (ax + ay) + (az + aw);
        acc += __shfl_down_sync(0xFFFFFFFFu, acc, 1);

        if (!half) {
            float pre = acc + xv;
            float a = (g < 200 || g >= 300) ? sigf(pre) : tanhfast(pre);
            gates_s[g] = a;   // already activated
        }
        __syncthreads();

        if (tid < H) {
            float iv = gates_s[tid];
            float fv = gates_s[H + tid];
            float gv = gates_s[2 * H + tid];
            float ov = gates_s[3 * H + tid];
            c = fv * c + iv * gv;
            float hval = ov * tanhfast(c);
            if (tid < 50) h_a[tid] = hval; else h_b[tid - 50] = hval;
            if (tid == last_s[t]) th[t * E] = hval;
        }
        __syncthreads();
    }
}

// ---------------- K4: final FC + sigmoid ----------------
__global__ void k_fc(const float* __restrict__ fcw,
                     const float* __restrict__ fcb,
                     float* __restrict__ out) {
    int warp = (blockIdx.x * blockDim.x + threadIdx.x) >> 5;
    int lane = threadIdx.x & 31;
    if (warp >= B) return;
    const float* th = g_trueh + warp * E;
    float acc = 0.f;
    #pragma unroll
    for (int k = 0; k < 4; k++) acc += th[lane + 32 * k] * fcw[lane + 32 * k];
    #pragma unroll
    for (int s = 16; s > 0; s >>= 1) acc += __shfl_down_sync(0xFFFFFFFFu, acc, s);
    if (lane == 0) out[warp] = 1.f / (1.f + __expf(-(acc + fcb[0])));
}

// ---------------- launcher: kernel launches ONLY ----------------
extern "C" void kernel_launch(void* const* d_in, const int* in_sizes, int n_in,
                              void* d_out, int out_size) {
    const int*   diag = (const int*)d_in[0];
    const float* mask = (const float*)d_in[1];
    const float* tab  = (const float*)d_in[2];
    const float* Wih  = (const float*)d_in[3];
    const float* Whh  = (const float*)d_in[4];
    const float* bih  = (const float*)d_in[5];
    const float* bhh  = (const float*)d_in[6];
    const float* fcw  = (const float*)d_in[7];
    const float* fcb  = (const float*)d_in[8];
    float* out = (float*)d_out;

    (void)in_sizes; (void)n_in; (void)out_size;

    k_detect<<<1, 256>>>(diag);
    k_last<<<B, 128>>>(mask);
    k_embed<<<(B * V) / 8, 256>>>(diag, mask, tab);
    k_gemm<<<dim3(M_TOT / BM, G4 / BN), 256>>>(Wih, bih, bhh);
    k_rec<<<E, 800>>>(Whh);
    k_fc<<<32, 256>>>(fcw, fcb, out);
}